// round 1
// baseline (speedup 1.0000x reference)
#include <cuda_runtime.h>

#define NN 100000
#define DD 128

// Scratch (static device globals — allocation-free at runtime)
__device__ float g_agg[NN * DD];     // 51.2 MB edge-sum accumulator
__device__ float g_deg[NN];          // in-degree (float)
__device__ float g_Wt[DD * DD];      // W transposed: Wt[k][j] = W[j][k]
__device__ int   g_is64;             // 1 if src/dst are int64, 0 if int32

// ---------------------------------------------------------------------------
// Detect index dtype: if the buffers are int64 (little-endian, values <2^31),
// every odd 32-bit word is zero. If int32, odd words hold real node ids
// (random in [0,100000)) — all-zero over 512 samples is impossible.
// ---------------------------------------------------------------------------
__global__ void detect_dtype_kernel(const unsigned int* __restrict__ src) {
    if (threadIdx.x == 0 && blockIdx.x == 0) {
        unsigned int acc = 0;
        #pragma unroll 8
        for (int i = 0; i < 512; ++i) acc |= src[2 * i + 1];
        g_is64 = (acc == 0u) ? 1 : 0;
    }
}

// ---------------------------------------------------------------------------
// Zero scratch (agg + deg) with float4 stores.
// ---------------------------------------------------------------------------
__global__ void zero_kernel() {
    int i = blockIdx.x * blockDim.x + threadIdx.x;
    float4 z = make_float4(0.f, 0.f, 0.f, 0.f);
    if (i < NN * DD / 4) reinterpret_cast<float4*>(g_agg)[i] = z;
    if (i < NN / 4)      reinterpret_cast<float4*>(g_deg)[i] = z;
}

// ---------------------------------------------------------------------------
// Transpose W (128x128) once so GEMM smem B-tile loads/stores are
// coalesced and conflict-free.
// ---------------------------------------------------------------------------
__global__ void transpose_kernel(const float* __restrict__ W) {
    int i = blockIdx.x * blockDim.x + threadIdx.x;   // i = j*128 + k
    if (i < DD * DD) g_Wt[(i & 127) * DD + (i >> 7)] = W[i];
}

// ---------------------------------------------------------------------------
// Edge scatter: one warp per edge. Lane l moves float4 l of the 128-float
// feature row. Vector reduction (red.global.add.v4.f32) quarters the atomic
// op count vs scalar atomicAdd. Lane 0 bumps the degree counter.
// ---------------------------------------------------------------------------
__global__ void scatter_kernel(const void* __restrict__ srcv,
                               const void* __restrict__ dstv,
                               const float4* __restrict__ feat4, int nE) {
    int gid = blockIdx.x * blockDim.x + threadIdx.x;
    int e = gid >> 5;
    if (e >= nE) return;
    int lane = gid & 31;

    long long s, d;
    if (g_is64) {
        s = reinterpret_cast<const long long*>(srcv)[e];
        d = reinterpret_cast<const long long*>(dstv)[e];
    } else {
        s = reinterpret_cast<const int*>(srcv)[e];
        d = reinterpret_cast<const int*>(dstv)[e];
    }

    float4 v = feat4[s * 32 + lane];
    float* p = &g_agg[d * DD + lane * 4];
    asm volatile("red.global.add.v4.f32 [%0], {%1,%2,%3,%4};"
                 :: "l"(p), "f"(v.x), "f"(v.y), "f"(v.z), "f"(v.w)
                 : "memory");
    if (lane == 0) atomicAdd(&g_deg[d], 1.0f);
}

// ---------------------------------------------------------------------------
// out[n] = (deg[n]>0 ? agg[n]/deg[n] : 0) @ W^T + b
// Tiled fp32 GEMM: block = 256 threads, tile 128x128, K-chunk 32,
// 8x8 register micro-tile per thread. Mean-divide fused into the A-tile load;
// deg==0 rows get inv=0 so acc=0 and the output is exactly b (matches ref).
// ---------------------------------------------------------------------------
__global__ __launch_bounds__(256) void gemm_kernel(
    const float* __restrict__ bias, float* __restrict__ out, int nrows) {
    __shared__ __align__(16) float Hs[128][32];   // h rows (pre-divided)
    __shared__ __align__(16) float Ws[32][128];   // Wt chunk: Ws[k][j]
    __shared__ float inv_s[128];

    const int row0 = blockIdx.x * 128;
    const int t  = threadIdx.x;
    const int tx = t & 15;          // 16 col-groups of 8
    const int ty = t >> 4;          // 16 row-groups of 8

    if (t < 128) {
        int r = row0 + t;
        float dg = (r < nrows) ? g_deg[r] : 0.f;
        inv_s[t] = (dg > 0.f) ? (1.f / dg) : 0.f;
    }
    __syncthreads();

    float acc[8][8];
    #pragma unroll
    for (int r = 0; r < 8; r++)
        #pragma unroll
        for (int c = 0; c < 8; c++) acc[r][c] = 0.f;

    for (int k0 = 0; k0 < DD; k0 += 32) {
        // A tile: 128 rows x 32 k, coalesced in k; divide by degree on load.
        #pragma unroll
        for (int i = 0; i < 16; i++) {
            int idx = t + i * 256;
            int r = idx >> 5, k = idx & 31;
            int gr = row0 + r;
            float v = (gr < nrows) ? g_agg[gr * DD + k0 + k] : 0.f;
            Hs[r][k] = v * inv_s[r];
        }
        // B tile: Wt rows k0..k0+31, coalesced in j, conflict-free STS.
        #pragma unroll
        for (int i = 0; i < 16; i++) {
            int idx = t + i * 256;
            int k = idx >> 7, j = idx & 127;
            Ws[k][j] = g_Wt[(k0 + k) * DD + j];
        }
        __syncthreads();

        #pragma unroll
        for (int k = 0; k < 32; k++) {
            float a[8];
            #pragma unroll
            for (int r = 0; r < 8; r++) a[r] = Hs[ty * 8 + r][k];  // broadcast
            float4 p0 = *reinterpret_cast<const float4*>(&Ws[k][tx * 8]);
            float4 p1 = *reinterpret_cast<const float4*>(&Ws[k][tx * 8 + 4]);
            float bb[8] = {p0.x, p0.y, p0.z, p0.w, p1.x, p1.y, p1.z, p1.w};
            #pragma unroll
            for (int r = 0; r < 8; r++)
                #pragma unroll
                for (int c = 0; c < 8; c++)
                    acc[r][c] = fmaf(a[r], bb[c], acc[r][c]);
        }
        __syncthreads();
    }

    float4 bv0 = *reinterpret_cast<const float4*>(&bias[tx * 8]);
    float4 bv1 = *reinterpret_cast<const float4*>(&bias[tx * 8 + 4]);
    #pragma unroll
    for (int r = 0; r < 8; r++) {
        int gr = row0 + ty * 8 + r;
        if (gr < nrows) {
            float4 o0 = make_float4(acc[r][0] + bv0.x, acc[r][1] + bv0.y,
                                    acc[r][2] + bv0.z, acc[r][3] + bv0.w);
            float4 o1 = make_float4(acc[r][4] + bv1.x, acc[r][5] + bv1.y,
                                    acc[r][6] + bv1.z, acc[r][7] + bv1.w);
            reinterpret_cast<float4*>(out)[gr * 32 + tx * 2]     = o0;
            reinterpret_cast<float4*>(out)[gr * 32 + tx * 2 + 1] = o1;
        }
    }
}

extern "C" void kernel_launch(void* const* d_in, const int* in_sizes, int n_in,
                              void* d_out, int out_size) {
    const float* feature = (const float*)d_in[0];   // [100000,128] f32
    const float* W       = (const float*)d_in[1];   // [128,128]   f32
    const float* bias    = (const float*)d_in[2];   // [128]       f32
    const void*  src     = d_in[3];                 // [625000] int64/int32
    const void*  dst     = d_in[4];                 // [625000] int64/int32
    float*       out     = (float*)d_out;           // [100000,128] f32

    const int nE = in_sizes[3];
    const int nN = in_sizes[0] / DD;

    detect_dtype_kernel<<<1, 32>>>((const unsigned int*)src);

    int zero_threads = NN * DD / 4;                  // covers deg too
    zero_kernel<<<(zero_threads + 255) / 256, 256>>>();

    transpose_kernel<<<(DD * DD + 255) / 256, 256>>>(W);

    long long scatter_threads = (long long)nE * 32;
    scatter_kernel<<<(unsigned)((scatter_threads + 255) / 256), 256>>>(
        src, dst, (const float4*)feature, nE);

    gemm_kernel<<<(nN + 127) / 128, 256>>>(bias, out, nN);
}

// round 3
// speedup vs baseline: 1.6821x; 1.6821x over previous
#include <cuda_runtime.h>
#include <cuda_bf16.h>
#include <cstdint>

#define NN 100000
#define DD 128

// Scratch (static device globals — allocation-free at runtime)
__device__ float g_agg[NN * DD];           // 51.2 MB edge-sum accumulator
__device__ float g_deg[NN];                // in-degree (float)
__device__ __nv_bfloat16 g_Whi[DD * DD];   // W split high (row-major [n][k])
__device__ __nv_bfloat16 g_Wlo[DD * DD];   // W split low
__device__ int g_is64;                     // 1 if src/dst are int64

// ---------------------------------------------------------------------------
// Index dtype detection (int64 vs int32): int64 values < 2^31 have all-zero
// odd 32-bit words; int32 node ids over 512 samples cannot.
// ---------------------------------------------------------------------------
__global__ void detect_dtype_kernel(const unsigned int* __restrict__ src) {
    if (threadIdx.x == 0 && blockIdx.x == 0) {
        unsigned int acc = 0;
        #pragma unroll 8
        for (int i = 0; i < 512; ++i) acc |= src[2 * i + 1];
        g_is64 = (acc == 0u) ? 1 : 0;
    }
}

__global__ void zero_kernel() {
    int i = blockIdx.x * blockDim.x + threadIdx.x;
    float4 z = make_float4(0.f, 0.f, 0.f, 0.f);
    if (i < NN * DD / 4) reinterpret_cast<float4*>(g_agg)[i] = z;
    if (i < NN / 4)      reinterpret_cast<float4*>(g_deg)[i] = z;
}

// Split W into bf16 hi/lo (Markidis): W ~= hi + lo to ~16 mantissa bits.
__global__ void wprep_kernel(const float* __restrict__ W) {
    int i = blockIdx.x * blockDim.x + threadIdx.x;
    if (i < DD * DD) {
        float w = W[i];
        __nv_bfloat16 hi = __float2bfloat16(w);
        g_Whi[i] = hi;
        g_Wlo[i] = __float2bfloat16(w - __bfloat162float(hi));
    }
}

// ---------------------------------------------------------------------------
// Edge scatter: 4 edges per warp, 8 lanes per edge, 4 float4 per lane.
// Gives each thread 4 independent load->red chains (MLP 4) vs 1 before.
// ---------------------------------------------------------------------------
__global__ void scatter_kernel(const void* __restrict__ srcv,
                               const void* __restrict__ dstv,
                               const float4* __restrict__ feat4, int nE) {
    int gid = blockIdx.x * blockDim.x + threadIdx.x;
    int warp = gid >> 5, lane = gid & 31;
    int e = warp * 4 + (lane >> 3);
    if (e >= nE) return;
    int li = lane & 7;

    long long s, d;
    if (g_is64) {
        s = reinterpret_cast<const long long*>(srcv)[e];
        d = reinterpret_cast<const long long*>(dstv)[e];
    } else {
        s = reinterpret_cast<const int*>(srcv)[e];
        d = reinterpret_cast<const int*>(dstv)[e];
    }

    float4 v[4];
    #pragma unroll
    for (int j = 0; j < 4; j++) v[j] = feat4[s * 32 + li + j * 8];
    #pragma unroll
    for (int j = 0; j < 4; j++) {
        float* p = &g_agg[d * DD + (li + j * 8) * 4];
        asm volatile("red.global.add.v4.f32 [%0], {%1,%2,%3,%4};"
                     :: "l"(p), "f"(v[j].x), "f"(v[j].y), "f"(v[j].z), "f"(v[j].w)
                     : "memory");
    }
    if (li == 0) atomicAdd(&g_deg[d], 1.0f);
}

// ---------------------------------------------------------------------------
// Split-bf16 GEMM via mma.sync.m16n8k16 (legal at compute_103, unlike tcgen05)
//   out[m] = (agg[m] * inv_deg[m]) @ W^T + b
// acc = Ahi*Bhi + Ahi*Blo + Alo*Bhi in fp32 accumulators; mean applied in
// epilogue (linear). Smem rows use stride 136 bf16 so b32 fragment loads are
// bank-conflict-free: word = row*68 + k/2 + (l%4), 68 mod 32 = 4.
// ---------------------------------------------------------------------------
#define STRIDE 136                       // bf16 elems per smem row
#define ROWB   (STRIDE * 2)              // 272 bytes per row
#define SA_HI  0
#define SA_LO  34816
#define SB_HI  69632
#define SB_LO  104448
#define SM_INV 139264
#define SM_TOTAL (139264 + 512)

__device__ __forceinline__ void mma16816(float* c, uint32_t a0, uint32_t a1,
                                         uint32_t a2, uint32_t a3,
                                         uint32_t b0, uint32_t b1) {
    asm volatile(
        "mma.sync.aligned.m16n8k16.row.col.f32.bf16.bf16.f32 "
        "{%0,%1,%2,%3}, {%4,%5,%6,%7}, {%8,%9}, {%0,%1,%2,%3};"
        : "+f"(c[0]), "+f"(c[1]), "+f"(c[2]), "+f"(c[3])
        : "r"(a0), "r"(a1), "r"(a2), "r"(a3), "r"(b0), "r"(b1));
}

__global__ __launch_bounds__(256, 1) void gcn_mma_kernel(
    const float* __restrict__ bias, float* __restrict__ out, int nrows) {
    extern __shared__ char smem[];
    const int t = threadIdx.x, wid = t >> 5, lane = t & 31;
    const int row0 = blockIdx.x * 128;
    const int q = lane >> 2, s = lane & 3;      // quad row / quad col
    const int warpM = (wid & 3) * 32;           // 4 warps over M
    const int warpN = (wid >> 2) * 64;          // 2 warps over N

    float* inv_s = reinterpret_cast<float*>(smem + SM_INV);
    if (t < 128) {
        int r = row0 + t;
        float dg = (r < nrows) ? g_deg[r] : 0.f;
        inv_s[t] = (dg > 0.f) ? (1.f / dg) : 0.f;
    }

    // Stage B (Whi/Wlo packed bf16x2, [n][k] k-contiguous) into strided smem.
    const uint32_t* whi = reinterpret_cast<const uint32_t*>(g_Whi);
    const uint32_t* wlo = reinterpret_cast<const uint32_t*>(g_Wlo);
    #pragma unroll
    for (int i = 0; i < 32; i++) {
        int p = t + i * 256;                    // p = n*64 + kp
        int n = p >> 6, kp = p & 63;
        uint32_t off = n * ROWB + kp * 4;
        *reinterpret_cast<uint32_t*>(smem + SB_HI + off) = whi[p];
        *reinterpret_cast<uint32_t*>(smem + SB_LO + off) = wlo[p];
    }
    // Stage A: load fp32 agg rows, split to bf16 hi/lo.
    #pragma unroll
    for (int i = 0; i < 32; i++) {
        int p = t + i * 256;                    // p = r*64 + kp
        int r = p >> 6, kp = p & 63;
        int gr = row0 + r;
        float2 v = make_float2(0.f, 0.f);
        if (gr < nrows) v = *reinterpret_cast<const float2*>(&g_agg[gr * DD + kp * 2]);
        __nv_bfloat16 h0 = __float2bfloat16(v.x);
        __nv_bfloat16 h1 = __float2bfloat16(v.y);
        __nv_bfloat16 l0 = __float2bfloat16(v.x - __bfloat162float(h0));
        __nv_bfloat16 l1 = __float2bfloat16(v.y - __bfloat162float(h1));
        uint32_t hip = ((uint32_t)__bfloat16_as_ushort(h1) << 16) | __bfloat16_as_ushort(h0);
        uint32_t lop = ((uint32_t)__bfloat16_as_ushort(l1) << 16) | __bfloat16_as_ushort(l0);
        uint32_t off = r * ROWB + kp * 4;
        *reinterpret_cast<uint32_t*>(smem + SA_HI + off) = hip;
        *reinterpret_cast<uint32_t*>(smem + SA_LO + off) = lop;
    }
    __syncthreads();

    float acc[2][8][4];
    #pragma unroll
    for (int mt = 0; mt < 2; mt++)
        #pragma unroll
        for (int nt = 0; nt < 8; nt++)
            #pragma unroll
            for (int c = 0; c < 4; c++) acc[mt][nt][c] = 0.f;

    #pragma unroll
    for (int pass = 0; pass < 3; pass++) {
        const char* Ab = smem + (pass < 2 ? SA_HI : SA_LO);
        const char* Bb = smem + (pass == 1 ? SB_LO : SB_HI);
        #pragma unroll
        for (int ks = 0; ks < 8; ks++) {
            const int k0 = ks * 16;
            uint32_t b0[8], b1[8];
            #pragma unroll
            for (int nt = 0; nt < 8; nt++) {
                uint32_t off = (warpN + nt * 8 + q) * ROWB + (k0 + s * 2) * 2;
                b0[nt] = *reinterpret_cast<const uint32_t*>(Bb + off);
                b1[nt] = *reinterpret_cast<const uint32_t*>(Bb + off + 16);
            }
            #pragma unroll
            for (int mt = 0; mt < 2; mt++) {
                uint32_t off = (warpM + mt * 16 + q) * ROWB + (k0 + s * 2) * 2;
                uint32_t a0 = *reinterpret_cast<const uint32_t*>(Ab + off);
                uint32_t a1 = *reinterpret_cast<const uint32_t*>(Ab + off + 8 * ROWB);
                uint32_t a2 = *reinterpret_cast<const uint32_t*>(Ab + off + 16);
                uint32_t a3 = *reinterpret_cast<const uint32_t*>(Ab + off + 8 * ROWB + 16);
                #pragma unroll
                for (int nt = 0; nt < 8; nt++)
                    mma16816(acc[mt][nt], a0, a1, a2, a3, b0[nt], b1[nt]);
            }
        }
    }

    // Epilogue: out[m][n] = acc*inv_deg[m] + bias[n]
    #pragma unroll
    for (int mt = 0; mt < 2; mt++) {
        int mb = warpM + mt * 16 + q;
        float invA = inv_s[mb];
        float invB = inv_s[mb + 8];
        int mA = row0 + mb, mB = mA + 8;
        #pragma unroll
        for (int nt = 0; nt < 8; nt++) {
            int n = warpN + nt * 8 + s * 2;
            float2 bb = *reinterpret_cast<const float2*>(&bias[n]);
            if (mA < nrows) {
                float2 o = make_float2(acc[mt][nt][0] * invA + bb.x,
                                       acc[mt][nt][1] * invA + bb.y);
                *reinterpret_cast<float2*>(&out[(size_t)mA * DD + n]) = o;
            }
            if (mB < nrows) {
                float2 o = make_float2(acc[mt][nt][2] * invB + bb.x,
                                       acc[mt][nt][3] * invB + bb.y);
                *reinterpret_cast<float2*>(&out[(size_t)mB * DD + n]) = o;
            }
        }
    }
}

extern "C" void kernel_launch(void* const* d_in, const int* in_sizes, int n_in,
                              void* d_out, int out_size) {
    const float* feature = (const float*)d_in[0];   // [100000,128] f32
    const float* W       = (const float*)d_in[1];   // [128,128]   f32
    const float* bias    = (const float*)d_in[2];   // [128]       f32
    const void*  src     = d_in[3];                 // [625000] int64/int32
    const void*  dst     = d_in[4];                 // [625000] int64/int32
    float*       out     = (float*)d_out;           // [100000,128] f32

    const int nE = in_sizes[3];
    const int nN = in_sizes[0] / DD;

    detect_dtype_kernel<<<1, 32>>>((const unsigned int*)src);

    int zero_threads = NN * DD / 4;
    zero_kernel<<<(zero_threads + 255) / 256, 256>>>();

    wprep_kernel<<<(DD * DD + 255) / 256, 256>>>(W);

    long long scatter_threads = (long long)nE * 8;   // 8 lanes per edge
    scatter_kernel<<<(unsigned)((scatter_threads + 255) / 256), 256>>>(
        src, dst, (const float4*)feature, nE);

    cudaFuncSetAttribute(gcn_mma_kernel,
                         cudaFuncAttributeMaxDynamicSharedMemorySize, SM_TOTAL);
    gcn_mma_kernel<<<(nN + 127) / 128, 256, SM_TOTAL>>>(bias, out, nN);
}